// round 1
// baseline (speedup 1.0000x reference)
#include <cuda_runtime.h>
#include <cstdint>

#define NN 8192
#define DD 512
#define INV_T 25.0f     // 1/0.04
#define EPS_KOLEO 1e-9f

typedef unsigned long long ull;

// ------------------- device scratch (no allocs allowed) -------------------
__device__ float g_z1n[NN * DD];
__device__ float g_z2n[NN * DD];
__device__ float g_rowsum[NN];
__device__ float g_colsum[NN];
__device__ float g_diag[NN];     // S_ii in logit units
__device__ int   g_max1[NN];     // ordered-int encoded row max of G1 (excl diag)
__device__ int   g_max2[NN];

// ------------------- helpers -------------------
__device__ __forceinline__ int enc_f(float f) {
    int i = __float_as_int(f);
    return i >= 0 ? i : i ^ 0x7FFFFFFF;
}
__device__ __forceinline__ float dec_f(int i) {
    return __int_as_float(i >= 0 ? i : i ^ 0x7FFFFFFF);
}

__device__ __forceinline__ ull pack2(float x, float y) {
    ull r;
    unsigned a = __float_as_uint(x), b = __float_as_uint(y);
    asm("mov.b64 %0, {%1, %2};" : "=l"(r) : "r"(a), "r"(b));
    return r;
}
__device__ __forceinline__ void unpack2(ull v, float& x, float& y) {
    unsigned a, b;
    asm("mov.b64 {%0, %1}, %2;" : "=r"(a), "=r"(b) : "l"(v));
    x = __uint_as_float(a);
    y = __uint_as_float(b);
}
// packed dual fp32 FMA (sm_100+): c = a*b + c elementwise on 2 lanes
__device__ __forceinline__ void ffma2(ull& c, ull a, ull b) {
    asm("fma.rn.f32x2 %0, %1, %2, %3;" : "=l"(c) : "l"(a), "l"(b), "l"(c));
}

// ------------------- row L2 normalization -------------------
__global__ void normalize_kernel(const float* __restrict__ z1,
                                 const float* __restrict__ z2) {
    int row = blockIdx.x;
    const float* src = blockIdx.y ? z2 : z1;
    float* dst = blockIdx.y ? g_z2n : g_z1n;
    int t = threadIdx.x;  // 128 threads, 4 floats each = 512
    float4 v = ((const float4*)(src + (size_t)row * DD))[t];
    float s = v.x * v.x + v.y * v.y + v.z * v.z + v.w * v.w;
#pragma unroll
    for (int o = 16; o; o >>= 1) s += __shfl_xor_sync(0xffffffffu, s, o);
    __shared__ float ws[4];
    if ((t & 31) == 0) ws[t >> 5] = s;
    __syncthreads();
    float tot = ws[0] + ws[1] + ws[2] + ws[3];
    float scale = 1.0f / fmaxf(sqrtf(tot), 1e-12f);
    v.x *= scale; v.y *= scale; v.z *= scale; v.w *= scale;
    ((float4*)(dst + (size_t)row * DD))[t] = v;
}

// ------------------- init scratch -------------------
__global__ void init_kernel() {
    int i = blockIdx.x * blockDim.x + threadIdx.x;
    if (i < NN) {
        g_rowsum[i] = 0.0f;
        g_colsum[i] = 0.0f;
        g_diag[i] = 0.0f;
        int e = enc_f(-2.0f);   // grams are in [-1,1]
        g_max1[i] = e;
        g_max2[i] = e;
    }
}

// =====================================================================
// Cross kernel: S = z1n @ z2n^T * INV_T.
// Tile 64 (rows) x 128 (cols), BK=32, 256 threads, 4x8 microtile via f32x2.
// Accumulates exp(logit) into g_rowsum / g_colsum, records diag logits.
// =====================================================================
__global__ __launch_bounds__(256) void cross_kernel() {
    __shared__ float As[32][64];    // [k][m]
    __shared__ float Bs[32][128];   // [k][n]
    __shared__ float scol[128];

    const int bj = blockIdx.x;   // col tile of 128
    const int bi = blockIdx.y;   // row tile of 64
    const int tid = threadIdx.x;
    const int tx = tid & 15;
    const int ty = tid >> 4;

    ull acc[4][4];
#pragma unroll
    for (int ii = 0; ii < 4; ii++)
#pragma unroll
        for (int jp = 0; jp < 4; jp++) acc[ii][jp] = 0ull;

    const float* __restrict__ A = g_z1n;
    const float* __restrict__ B = g_z2n;

    for (int kt = 0; kt < DD; kt += 32) {
        // load A tile: 64x32 = 512 float4, 2 per thread
#pragma unroll
        for (int s = 0; s < 2; s++) {
            int f = tid + 256 * s;
            int m = f >> 3, kq = f & 7;
            float4 v = *(const float4*)&A[(size_t)(bi * 64 + m) * DD + kt + kq * 4];
            As[kq * 4 + 0][m] = v.x;
            As[kq * 4 + 1][m] = v.y;
            As[kq * 4 + 2][m] = v.z;
            As[kq * 4 + 3][m] = v.w;
        }
        // load B tile: 128x32 = 1024 float4, 4 per thread
#pragma unroll
        for (int s = 0; s < 4; s++) {
            int f = tid + 256 * s;
            int m = f >> 3, kq = f & 7;
            float4 v = *(const float4*)&B[(size_t)(bj * 128 + m) * DD + kt + kq * 4];
            Bs[kq * 4 + 0][m] = v.x;
            Bs[kq * 4 + 1][m] = v.y;
            Bs[kq * 4 + 2][m] = v.z;
            Bs[kq * 4 + 3][m] = v.w;
        }
        __syncthreads();
#pragma unroll
        for (int k = 0; k < 32; k++) {
            float4 a = *(const float4*)&As[k][ty * 4];
            const ulonglong2* bp = (const ulonglong2*)&Bs[k][tx * 8];
            ulonglong2 b01 = bp[0];
            ulonglong2 b23 = bp[1];
            ull A0 = pack2(a.x, a.x), A1 = pack2(a.y, a.y);
            ull A2 = pack2(a.z, a.z), A3 = pack2(a.w, a.w);
            ffma2(acc[0][0], A0, b01.x); ffma2(acc[0][1], A0, b01.y);
            ffma2(acc[0][2], A0, b23.x); ffma2(acc[0][3], A0, b23.y);
            ffma2(acc[1][0], A1, b01.x); ffma2(acc[1][1], A1, b01.y);
            ffma2(acc[1][2], A1, b23.x); ffma2(acc[1][3], A1, b23.y);
            ffma2(acc[2][0], A2, b01.x); ffma2(acc[2][1], A2, b01.y);
            ffma2(acc[2][2], A2, b23.x); ffma2(acc[2][3], A2, b23.y);
            ffma2(acc[3][0], A3, b01.x); ffma2(acc[3][1], A3, b01.y);
            ffma2(acc[3][2], A3, b23.x); ffma2(acc[3][3], A3, b23.y);
        }
        __syncthreads();
    }

    // ---------------- epilogue ----------------
    const int rbase = bi * 64 + ty * 4;
    const int cbase = bj * 128 + tx * 8;

    float cs[8];
#pragma unroll
    for (int j = 0; j < 8; j++) cs[j] = 0.0f;

#pragma unroll
    for (int ii = 0; ii < 4; ii++) {
        int r = rbase + ii;
        float rs = 0.0f;
#pragma unroll
        for (int jp = 0; jp < 4; jp++) {
            float x, y;
            unpack2(acc[ii][jp], x, y);
            float lx = x * INV_T, ly = y * INV_T;
            int cx = cbase + jp * 2;
            if (r == cx) g_diag[r] = lx;
            if (r == cx + 1) g_diag[r] = ly;
            float ex = __expf(lx), ey = __expf(ly);
            rs += ex + ey;
            cs[jp * 2] += ex;
            cs[jp * 2 + 1] += ey;
        }
        // reduce row sum across the 16 tx lanes (lanes 0-15 / 16-31 in warp)
        rs += __shfl_xor_sync(0xffffffffu, rs, 1);
        rs += __shfl_xor_sync(0xffffffffu, rs, 2);
        rs += __shfl_xor_sync(0xffffffffu, rs, 4);
        rs += __shfl_xor_sync(0xffffffffu, rs, 8);
        if (tx == 0) atomicAdd(&g_rowsum[r], rs);
    }

    if (tid < 128) scol[tid] = 0.0f;
    __syncthreads();
#pragma unroll
    for (int j = 0; j < 8; j++) atomicAdd(&scol[tx * 8 + j], cs[j]);
    __syncthreads();
    if (tid < 128) atomicAdd(&g_colsum[bj * 128 + tid], scol[tid]);
}

// =====================================================================
// Gram kernel (symmetric): G = z @ z^T for z in {z1n, z2n}.
// Only tiles intersecting the lower triangle are computed (max is
// idempotent so straddle over-coverage is harmless). Each off-diagonal
// element g(r,c), r!=c, updates rowmax[r] and rowmax[c].
// =====================================================================
template <int W>
__global__ __launch_bounds__(256) void gram_kernel() {
    const int bj = blockIdx.x;
    const int bi = blockIdx.y;
    // skip tiles entirely above the diagonal
    if (bj * 128 > bi * 64 + 63) return;

    __shared__ float As[32][64];
    __shared__ float Bs[32][128];
    __shared__ int smax[128];

    const int tid = threadIdx.x;
    const int tx = tid & 15;
    const int ty = tid >> 4;

    const float* __restrict__ Z = W ? g_z2n : g_z1n;
    int* __restrict__ mx = W ? g_max2 : g_max1;

    ull acc[4][4];
#pragma unroll
    for (int ii = 0; ii < 4; ii++)
#pragma unroll
        for (int jp = 0; jp < 4; jp++) acc[ii][jp] = 0ull;

    for (int kt = 0; kt < DD; kt += 32) {
#pragma unroll
        for (int s = 0; s < 2; s++) {
            int f = tid + 256 * s;
            int m = f >> 3, kq = f & 7;
            float4 v = *(const float4*)&Z[(size_t)(bi * 64 + m) * DD + kt + kq * 4];
            As[kq * 4 + 0][m] = v.x;
            As[kq * 4 + 1][m] = v.y;
            As[kq * 4 + 2][m] = v.z;
            As[kq * 4 + 3][m] = v.w;
        }
#pragma unroll
        for (int s = 0; s < 4; s++) {
            int f = tid + 256 * s;
            int m = f >> 3, kq = f & 7;
            float4 v = *(const float4*)&Z[(size_t)(bj * 128 + m) * DD + kt + kq * 4];
            Bs[kq * 4 + 0][m] = v.x;
            Bs[kq * 4 + 1][m] = v.y;
            Bs[kq * 4 + 2][m] = v.z;
            Bs[kq * 4 + 3][m] = v.w;
        }
        __syncthreads();
#pragma unroll
        for (int k = 0; k < 32; k++) {
            float4 a = *(const float4*)&As[k][ty * 4];
            const ulonglong2* bp = (const ulonglong2*)&Bs[k][tx * 8];
            ulonglong2 b01 = bp[0];
            ulonglong2 b23 = bp[1];
            ull A0 = pack2(a.x, a.x), A1 = pack2(a.y, a.y);
            ull A2 = pack2(a.z, a.z), A3 = pack2(a.w, a.w);
            ffma2(acc[0][0], A0, b01.x); ffma2(acc[0][1], A0, b01.y);
            ffma2(acc[0][2], A0, b23.x); ffma2(acc[0][3], A0, b23.y);
            ffma2(acc[1][0], A1, b01.x); ffma2(acc[1][1], A1, b01.y);
            ffma2(acc[1][2], A1, b23.x); ffma2(acc[1][3], A1, b23.y);
            ffma2(acc[2][0], A2, b01.x); ffma2(acc[2][1], A2, b01.y);
            ffma2(acc[2][2], A2, b23.x); ffma2(acc[2][3], A2, b23.y);
            ffma2(acc[3][0], A3, b01.x); ffma2(acc[3][1], A3, b01.y);
            ffma2(acc[3][2], A3, b23.x); ffma2(acc[3][3], A3, b23.y);
        }
        __syncthreads();
    }

    // ---------------- epilogue: row/col max excluding diagonal ----------------
    const int rbase = bi * 64 + ty * 4;
    const int cbase = bj * 128 + tx * 8;

    float cm[8];
#pragma unroll
    for (int j = 0; j < 8; j++) cm[j] = -2.0f;

#pragma unroll
    for (int ii = 0; ii < 4; ii++) {
        int r = rbase + ii;
        float rm = -2.0f;
#pragma unroll
        for (int jp = 0; jp < 4; jp++) {
            float x, y;
            unpack2(acc[ii][jp], x, y);
            int cx = cbase + jp * 2;
            if (r != cx) {
                rm = fmaxf(rm, x);
                cm[jp * 2] = fmaxf(cm[jp * 2], x);
            }
            if (r != cx + 1) {
                rm = fmaxf(rm, y);
                cm[jp * 2 + 1] = fmaxf(cm[jp * 2 + 1], y);
            }
        }
        rm = fmaxf(rm, __shfl_xor_sync(0xffffffffu, rm, 1));
        rm = fmaxf(rm, __shfl_xor_sync(0xffffffffu, rm, 2));
        rm = fmaxf(rm, __shfl_xor_sync(0xffffffffu, rm, 4));
        rm = fmaxf(rm, __shfl_xor_sync(0xffffffffu, rm, 8));
        if (tx == 0) atomicMax(&mx[r], enc_f(rm));
    }

    if (tid < 128) smax[tid] = enc_f(-2.0f);
    __syncthreads();
#pragma unroll
    for (int j = 0; j < 8; j++) atomicMax(&smax[tx * 8 + j], enc_f(cm[j]));
    __syncthreads();
    if (tid < 128) atomicMax(&mx[bj * 128 + tid], smax[tid]);
}

// ------------------- final scalar reduction -------------------
__global__ void finalize_kernel(float* __restrict__ out) {
    const int t = threadIdx.x;  // 256
    float s12 = 0.0f, s21 = 0.0f, k1 = 0.0f, k2 = 0.0f;
    for (int i = t; i < NN; i += 256) {
        float d = g_diag[i];
        s12 += logf(g_rowsum[i]) - d;
        s21 += logf(g_colsum[i]) - d;
        float m1 = dec_f(g_max1[i]);
        float m2 = dec_f(g_max2[i]);
        float d1 = sqrtf(fmaxf(2.0f - 2.0f * m1, 0.0f));
        float d2 = sqrtf(fmaxf(2.0f - 2.0f * m2, 0.0f));
        k1 += logf(d1 + EPS_KOLEO);
        k2 += logf(d2 + EPS_KOLEO);
    }
    __shared__ float sh[256];
    float vals[4] = {s12, s21, k1, k2};
    float red[4];
#pragma unroll
    for (int q = 0; q < 4; q++) {
        sh[t] = vals[q];
        __syncthreads();
        for (int o = 128; o; o >>= 1) {
            if (t < o) sh[t] += sh[t + o];
            __syncthreads();
        }
        red[q] = sh[0];
        __syncthreads();
    }
    if (t == 0) {
        float contrast = (red[0] + red[1]) / (2.0f * NN);
        float koleo = -(red[2] + red[3]) / (2.0f * NN);
        out[0] = contrast + 0.1f * koleo;
    }
}

// ------------------- launch -------------------
extern "C" void kernel_launch(void* const* d_in, const int* in_sizes, int n_in,
                              void* d_out, int out_size) {
    const float* z1 = (const float*)d_in[0];
    const float* z2 = (const float*)d_in[1];
    float* out = (float*)d_out;

    normalize_kernel<<<dim3(NN, 2), 128>>>(z1, z2);
    init_kernel<<<NN / 256, 256>>>();
    cross_kernel<<<dim3(64, 128), 256>>>();
    gram_kernel<0><<<dim3(64, 128), 256>>>();
    gram_kernel<1><<<dim3(64, 128), 256>>>();
    finalize_kernel<<<1, 256>>>(out);
}

// round 3
// speedup vs baseline: 10.8100x; 10.8100x over previous
#include <cuda_runtime.h>
#include <cuda_bf16.h>
#include <cstdint>

#define NN 8192
#define DD 512
#define INV_T 25.0f
#define EPS_KOLEO 1e-9f

// ------------------- device scratch -------------------
__device__ __nv_bfloat16 g_zb1[NN * DD];
__device__ __nv_bfloat16 g_zb2[NN * DD];
__device__ float g_rowsum[NN];
__device__ float g_colsum[NN];
__device__ float g_diag[NN];
__device__ int   g_max1[NN];
__device__ int   g_max2[NN];

// ------------------- helpers -------------------
__device__ __forceinline__ int enc_f(float f) {
    int i = __float_as_int(f);
    return i >= 0 ? i : i ^ 0x7FFFFFFF;
}
__device__ __forceinline__ float dec_f(int i) {
    return __int_as_float(i >= 0 ? i : i ^ 0x7FFFFFFF);
}
__device__ __forceinline__ uint32_t smem_u32(const void* p) {
    uint32_t a;
    asm("{ .reg .u64 t; cvta.to.shared.u64 t, %1; cvt.u32.u64 %0, t; }"
        : "=r"(a) : "l"(p));
    return a;
}
__device__ __forceinline__ void cp16(uint32_t saddr, const void* g) {
    asm volatile("cp.async.cg.shared.global [%0], [%1], 16;" :: "r"(saddr), "l"(g));
}
__device__ __forceinline__ void cp_commit() {
    asm volatile("cp.async.commit_group;" ::: "memory");
}
__device__ __forceinline__ void cp_wait1() {
    asm volatile("cp.async.wait_group 1;" ::: "memory");
}
__device__ __forceinline__ void cp_wait0() {
    asm volatile("cp.async.wait_group 0;" ::: "memory");
}
__device__ __forceinline__ void ldsm_x4(uint32_t* r, uint32_t a) {
    asm volatile("ldmatrix.sync.aligned.m8n8.x4.shared.b16 {%0,%1,%2,%3}, [%4];"
                 : "=r"(r[0]), "=r"(r[1]), "=r"(r[2]), "=r"(r[3]) : "r"(a));
}
__device__ __forceinline__ void ldsm_x2(uint32_t* r, uint32_t a) {
    asm volatile("ldmatrix.sync.aligned.m8n8.x2.shared.b16 {%0,%1}, [%2];"
                 : "=r"(r[0]), "=r"(r[1]) : "r"(a));
}
__device__ __forceinline__ void mma_bf16(float* c, const uint32_t* a, const uint32_t* b) {
    asm volatile(
        "mma.sync.aligned.m16n8k16.row.col.f32.bf16.bf16.f32 "
        "{%0,%1,%2,%3}, {%4,%5,%6,%7}, {%8,%9}, {%0,%1,%2,%3};"
        : "+f"(c[0]), "+f"(c[1]), "+f"(c[2]), "+f"(c[3])
        : "r"(a[0]), "r"(a[1]), "r"(a[2]), "r"(a[3]), "r"(b[0]), "r"(b[1]));
}

// ------------------- normalization -> bf16 -------------------
__global__ void normalize_kernel(const float* __restrict__ z1,
                                 const float* __restrict__ z2) {
    int row = blockIdx.x;
    const float* src = blockIdx.y ? z2 : z1;
    __nv_bfloat16* dst = blockIdx.y ? g_zb2 : g_zb1;
    int t = threadIdx.x;  // 128 threads x 4 floats
    float4 v = ((const float4*)(src + (size_t)row * DD))[t];
    float s = v.x * v.x + v.y * v.y + v.z * v.z + v.w * v.w;
#pragma unroll
    for (int o = 16; o; o >>= 1) s += __shfl_xor_sync(0xffffffffu, s, o);
    __shared__ float ws[4];
    if ((t & 31) == 0) ws[t >> 5] = s;
    __syncthreads();
    float tot = ws[0] + ws[1] + ws[2] + ws[3];
    float scale = 1.0f / fmaxf(sqrtf(tot), 1e-12f);
    __nv_bfloat162 p0 = __floats2bfloat162_rn(v.x * scale, v.y * scale);
    __nv_bfloat162 p1 = __floats2bfloat162_rn(v.z * scale, v.w * scale);
    __nv_bfloat162* d = (__nv_bfloat162*)(dst + (size_t)row * DD);
    d[t * 2 + 0] = p0;
    d[t * 2 + 1] = p1;
}

__global__ void init_kernel() {
    int i = blockIdx.x * blockDim.x + threadIdx.x;
    if (i < NN) {
        g_rowsum[i] = 0.0f;
        g_colsum[i] = 0.0f;
        g_diag[i] = 0.0f;
        int e = enc_f(-2.0f);
        g_max1[i] = e;
        g_max2[i] = e;
    }
}

// =====================================================================
// HMMA GEMM. CTA tile 128x128, BK=32 (16 chunks), 2-stage cp.async.
// 8 warps in 2x4 grid, warp tile 64x32, 4x4 m16n8k16 fragments.
// MODE 0: cross (z1 @ z2^T): exp/rowsum/colsum/diag
// MODE 1/2: gram of z1/z2 (triangle only): row/col max excl diag
// =====================================================================
#define PITCH 80   // bytes per 32-elem bf16 row in smem (64B data + 16B pad)

template <int MODE>
__global__ __launch_bounds__(256, 2) void gemm_kernel() {
    const int bj = blockIdx.x;
    const int bi = blockIdx.y;
    if (MODE != 0 && bj > bi) return;   // triangle only

    __shared__ __align__(16) char stA[2][128 * PITCH];
    __shared__ __align__(16) char stB[2][128 * PITCH];
    __shared__ int sred[256];           // [0:128) rows, [128:256) cols

    const int tid = threadIdx.x;
    const int wid = tid >> 5;
    const int lane = tid & 31;
    const int wrow = wid >> 2;          // 0..1
    const int wcol = wid & 3;           // 0..3
    const int wm = wrow * 64;
    const int wn = wcol * 32;

    const __nv_bfloat16* __restrict__ A = (MODE == 2) ? g_zb2 : g_zb1;
    const __nv_bfloat16* __restrict__ B = (MODE == 1) ? g_zb1 : g_zb2;

    const size_t arow0 = (size_t)bi * 128;
    const size_t brow0 = (size_t)bj * 128;

    const uint32_t sA0 = smem_u32(stA[0]);
    const uint32_t sB0 = smem_u32(stB[0]);
    const uint32_t sA1 = smem_u32(stA[1]);
    const uint32_t sB1 = smem_u32(stB[1]);

    // cp.async mapping: idx -> (row, 16B chunk)
    const int ldrow = tid >> 2;         // 0..63 (two iters cover 128)
    const int ldc16 = tid & 3;          // 0..3

    auto load_chunk = [&](int kc, int s) {
        uint32_t sA = s ? sA1 : sA0;
        uint32_t sB = s ? sB1 : sB0;
#pragma unroll
        for (int it = 0; it < 2; it++) {
            int row = ldrow + it * 64;
            uint32_t off = row * PITCH + ldc16 * 16;
            cp16(sA + off, A + (arow0 + row) * DD + kc * 32 + ldc16 * 8);
            cp16(sB + off, B + (brow0 + row) * DD + kc * 32 + ldc16 * 8);
        }
        cp_commit();
    };

    float acc[4][4][4];
#pragma unroll
    for (int mi = 0; mi < 4; mi++)
#pragma unroll
        for (int ni = 0; ni < 4; ni++)
#pragma unroll
            for (int q = 0; q < 4; q++) acc[mi][ni][q] = 0.0f;

    load_chunk(0, 0);

    for (int i = 0; i < 16; i++) {
        if (i < 15) load_chunk(i + 1, (i + 1) & 1);
        if (i < 15) cp_wait1(); else cp_wait0();
        __syncthreads();

        uint32_t sA = (i & 1) ? sA1 : sA0;
        uint32_t sB = (i & 1) ? sB1 : sB0;
        // precompute per-lane base addrs
        uint32_t aBase = sA + (wm + (lane & 15)) * PITCH + (lane >> 4) * 16;
        uint32_t bBase = sB + (wn + (lane & 7)) * PITCH + ((lane >> 3) & 1) * 16;

#pragma unroll
        for (int k16 = 0; k16 < 2; k16++) {
            uint32_t a[4][4], b[4][2];
#pragma unroll
            for (int mi = 0; mi < 4; mi++)
                ldsm_x4(a[mi], aBase + mi * 16 * PITCH + k16 * 32);
#pragma unroll
            for (int ni = 0; ni < 4; ni++)
                ldsm_x2(b[ni], bBase + ni * 8 * PITCH + k16 * 32);
#pragma unroll
            for (int mi = 0; mi < 4; mi++)
#pragma unroll
                for (int ni = 0; ni < 4; ni++)
                    mma_bf16(acc[mi][ni], a[mi], b[ni]);
        }
        __syncthreads();
    }

    // ---------------- epilogue ----------------
    // fragment element mapping: g = lane>>2, t = lane&3
    // c0:(r=g,    c=2t) c1:(r=g,    c=2t+1)
    // c2:(r=g+8,  c=2t) c3:(r=g+8,  c=2t+1)
    const int g = lane >> 2;
    const int t4 = lane & 3;

    if (MODE == 0) {
        float* sf = (float*)sred;
        if (tid < 128) { sf[tid] = 0.0f; sf[128 + tid] = 0.0f; }
        __syncthreads();

        float colacc[4][2];
#pragma unroll
        for (int ni = 0; ni < 4; ni++) { colacc[ni][0] = 0.0f; colacc[ni][1] = 0.0f; }

#pragma unroll
        for (int mi = 0; mi < 4; mi++) {
            int gr0 = bi * 128 + wm + mi * 16 + g;
            int gr1 = gr0 + 8;
            float row0 = 0.0f, row1 = 0.0f;
#pragma unroll
            for (int ni = 0; ni < 4; ni++) {
                int gc0 = bj * 128 + wn + ni * 8 + t4 * 2;
                float l00 = acc[mi][ni][0] * INV_T;
                float l01 = acc[mi][ni][1] * INV_T;
                float l10 = acc[mi][ni][2] * INV_T;
                float l11 = acc[mi][ni][3] * INV_T;
                if (gr0 == gc0)     g_diag[gr0] = l00;
                if (gr0 == gc0 + 1) g_diag[gr0] = l01;
                if (gr1 == gc0)     g_diag[gr1] = l10;
                if (gr1 == gc0 + 1) g_diag[gr1] = l11;
                float e00 = __expf(l00), e01 = __expf(l01);
                float e10 = __expf(l10), e11 = __expf(l11);
                row0 += e00 + e01;
                row1 += e10 + e11;
                colacc[ni][0] += e00 + e10;
                colacc[ni][1] += e01 + e11;
            }
            row0 += __shfl_xor_sync(0xffffffffu, row0, 1);
            row0 += __shfl_xor_sync(0xffffffffu, row0, 2);
            row1 += __shfl_xor_sync(0xffffffffu, row1, 1);
            row1 += __shfl_xor_sync(0xffffffffu, row1, 2);
            if (t4 == 0) {
                atomicAdd(&sf[wm + mi * 16 + g], row0);
                atomicAdd(&sf[wm + mi * 16 + g + 8], row1);
            }
        }
#pragma unroll
        for (int ni = 0; ni < 4; ni++) {
#pragma unroll
            for (int j = 0; j < 2; j++) {
                float v = colacc[ni][j];
                v += __shfl_xor_sync(0xffffffffu, v, 4);
                v += __shfl_xor_sync(0xffffffffu, v, 8);
                v += __shfl_xor_sync(0xffffffffu, v, 16);
                if (lane < 4)
                    atomicAdd(&sf[128 + wn + ni * 8 + (lane & 3) * 2 + j], v);
            }
        }
        __syncthreads();
        if (tid < 128) {
            atomicAdd(&g_rowsum[bi * 128 + tid], sf[tid]);
            atomicAdd(&g_colsum[bj * 128 + tid], sf[128 + tid]);
        }
    } else {
        int* __restrict__ mx = (MODE == 1) ? g_max1 : g_max2;
        const int encneg = enc_f(-2.0f);
        if (tid < 128) { sred[tid] = encneg; sred[128 + tid] = encneg; }
        __syncthreads();

        float colm[4][2];
#pragma unroll
        for (int ni = 0; ni < 4; ni++) { colm[ni][0] = -2.0f; colm[ni][1] = -2.0f; }

#pragma unroll
        for (int mi = 0; mi < 4; mi++) {
            int gr0 = bi * 128 + wm + mi * 16 + g;
            int gr1 = gr0 + 8;
            float row0 = -2.0f, row1 = -2.0f;
#pragma unroll
            for (int ni = 0; ni < 4; ni++) {
                int gc0 = bj * 128 + wn + ni * 8 + t4 * 2;
                float v00 = acc[mi][ni][0];
                float v01 = acc[mi][ni][1];
                float v10 = acc[mi][ni][2];
                float v11 = acc[mi][ni][3];
                if (gr0 == gc0)     v00 = -2.0f;
                if (gr0 == gc0 + 1) v01 = -2.0f;
                if (gr1 == gc0)     v10 = -2.0f;
                if (gr1 == gc0 + 1) v11 = -2.0f;
                row0 = fmaxf(row0, fmaxf(v00, v01));
                row1 = fmaxf(row1, fmaxf(v10, v11));
                colm[ni][0] = fmaxf(colm[ni][0], fmaxf(v00, v10));
                colm[ni][1] = fmaxf(colm[ni][1], fmaxf(v01, v11));
            }
            row0 = fmaxf(row0, __shfl_xor_sync(0xffffffffu, row0, 1));
            row0 = fmaxf(row0, __shfl_xor_sync(0xffffffffu, row0, 2));
            row1 = fmaxf(row1, __shfl_xor_sync(0xffffffffu, row1, 1));
            row1 = fmaxf(row1, __shfl_xor_sync(0xffffffffu, row1, 2));
            if (t4 == 0) {
                atomicMax(&sred[wm + mi * 16 + g], enc_f(row0));
                atomicMax(&sred[wm + mi * 16 + g + 8], enc_f(row1));
            }
        }
#pragma unroll
        for (int ni = 0; ni < 4; ni++) {
#pragma unroll
            for (int j = 0; j < 2; j++) {
                float v = colm[ni][j];
                v = fmaxf(v, __shfl_xor_sync(0xffffffffu, v, 4));
                v = fmaxf(v, __shfl_xor_sync(0xffffffffu, v, 8));
                v = fmaxf(v, __shfl_xor_sync(0xffffffffu, v, 16));
                if (lane < 4)
                    atomicMax(&sred[128 + wn + ni * 8 + (lane & 3) * 2 + j], enc_f(v));
            }
        }
        __syncthreads();
        if (tid < 128) {
            atomicMax(&mx[bi * 128 + tid], sred[tid]);
            atomicMax(&mx[bj * 128 + tid], sred[128 + tid]);
        }
    }
}

// ------------------- final scalar reduction -------------------
__global__ void finalize_kernel(float* __restrict__ out) {
    const int t = threadIdx.x;  // 256
    float s12 = 0.0f, s21 = 0.0f, k1 = 0.0f, k2 = 0.0f;
    for (int i = t; i < NN; i += 256) {
        float d = g_diag[i];
        s12 += logf(g_rowsum[i]) - d;
        s21 += logf(g_colsum[i]) - d;
        float m1 = dec_f(g_max1[i]);
        float m2 = dec_f(g_max2[i]);
        float d1 = sqrtf(fmaxf(2.0f - 2.0f * m1, 0.0f));
        float d2 = sqrtf(fmaxf(2.0f - 2.0f * m2, 0.0f));
        k1 += logf(d1 + EPS_KOLEO);
        k2 += logf(d2 + EPS_KOLEO);
    }
    __shared__ float sh[256];
    float vals[4] = {s12, s21, k1, k2};
    float red[4];
#pragma unroll
    for (int q = 0; q < 4; q++) {
        sh[t] = vals[q];
        __syncthreads();
        for (int o = 128; o; o >>= 1) {
            if (t < o) sh[t] += sh[t + o];
            __syncthreads();
        }
        red[q] = sh[0];
        __syncthreads();
    }
    if (t == 0) {
        float contrast = (red[0] + red[1]) / (2.0f * NN);
        float koleo = -(red[2] + red[3]) / (2.0f * NN);
        out[0] = contrast + 0.1f * koleo;
    }
}

// ------------------- launch -------------------
extern "C" void kernel_launch(void* const* d_in, const int* in_sizes, int n_in,
                              void* d_out, int out_size) {
    const float* z1 = (const float*)d_in[0];
    const float* z2 = (const float*)d_in[1];
    float* out = (float*)d_out;

    normalize_kernel<<<dim3(NN, 2), 128>>>(z1, z2);
    init_kernel<<<NN / 256, 256>>>();
    gemm_kernel<0><<<dim3(64, 64), 256>>>();
    gemm_kernel<1><<<dim3(64, 64), 256>>>();
    gemm_kernel<2><<<dim3(64, 64), 256>>>();
    finalize_kernel<<<1, 256>>>(out);
}